// round 6
// baseline (speedup 1.0000x reference)
#include <cuda_runtime.h>
#include <math.h>

#define Bn   32
#define Tt   512
#define Dm   1024
#define Uc   1024
#define BBu  2048
#define NTOK 16384   // Bn*Tt
#define GS   148     // persistent scan grid (<= SM count -> co-resident)

// ---------------- scratch (device globals; no allocs allowed) ----------------
__device__ float g_xn[NTOK * Dm];        // 64 MB
__device__ float g_cfcx[NTOK * Dm];      // 64 MB
__device__ float g_px[NTOK * BBu];       // 128 MB : precomputed x-part of backbone L0 (+bias)
__device__ float g_cfcout[NTOK * Uc];    // 64 MB
__device__ float g_h[Bn * Uc];
__device__ float g_bb1[Bn * BBu];
__device__ float g_bb2[Bn * BBu];
__device__ unsigned long long g_bar;     // monotonic grid-barrier counter

// ---------------- LayerNorm ----------------
__global__ __launch_bounds__(256) void ln_kernel(const float* __restrict__ x,
                                                 const float* __restrict__ w,
                                                 const float* __restrict__ b,
                                                 float* __restrict__ xn) {
    int row = blockIdx.x;
    int t = threadIdx.x;
    const float4* xr = (const float4*)(x + (size_t)row * Dm);
    float4 v = xr[t];
    float s  = v.x + v.y + v.z + v.w;
    float ss = v.x * v.x + v.y * v.y + v.z * v.z + v.w * v.w;
#pragma unroll
    for (int o = 16; o > 0; o >>= 1) {
        s  += __shfl_xor_sync(0xffffffffu, s, o);
        ss += __shfl_xor_sync(0xffffffffu, ss, o);
    }
    __shared__ float sred[16];
    __shared__ float s_mu, s_rs;
    int warp = t >> 5, lane = t & 31;
    if (lane == 0) { sred[warp] = s; sred[8 + warp] = ss; }
    __syncthreads();
    if (t == 0) {
        float S = 0.f, SS = 0.f;
#pragma unroll
        for (int i = 0; i < 8; i++) { S += sred[i]; SS += sred[8 + i]; }
        float mu = S * (1.0f / Dm);
        float var = SS * (1.0f / Dm) - mu * mu;
        s_mu = mu;
        s_rs = rsqrtf(var + 1e-5f);
    }
    __syncthreads();
    float mu = s_mu, rs = s_rs;
    float4 wv = ((const float4*)w)[t];
    float4 bv = ((const float4*)b)[t];
    float4 o;
    o.x = (v.x - mu) * rs * wv.x + bv.x;
    o.y = (v.y - mu) * rs * wv.y + bv.y;
    o.z = (v.z - mu) * rs * wv.z + bv.z;
    o.w = (v.w - mu) * rs * wv.w + bv.w;
    ((float4*)(xn + (size_t)row * Dm))[t] = o;
}

// ---------------- big SGEMM: C[M,N] = A[M,K]@B[K,N] (+bias) (+resid) ----------------
__global__ __launch_bounds__(256) void sgemm_k(const float* __restrict__ A,
                                               const float* __restrict__ B,
                                               const float* __restrict__ bias,
                                               const float* __restrict__ resid,
                                               float* __restrict__ C,
                                               int M, int N, int K) {
    __shared__ float As[8][128];
    __shared__ float Bs[8][128];
    int tid = threadIdx.x;
    int m0 = blockIdx.y * 128, n0 = blockIdx.x * 128;
    int tx = tid & 15, ty = tid >> 4;
    float acc[8][8];
#pragma unroll
    for (int i = 0; i < 8; i++)
#pragma unroll
        for (int j = 0; j < 8; j++) acc[i][j] = 0.f;

    int arow = tid >> 1, ac4 = (tid & 1) * 4;
    int brow = tid >> 5, bc4 = (tid & 31) * 4;
    const float* Ap = A + (size_t)(m0 + arow) * K + ac4;
    const float* Bp = B + (size_t)brow * N + n0 + bc4;

    for (int k0 = 0; k0 < K; k0 += 8) {
        float4 av = *(const float4*)(Ap + k0);
        float4 bv = *(const float4*)(Bp + (size_t)k0 * N);
        As[ac4 + 0][arow] = av.x;
        As[ac4 + 1][arow] = av.y;
        As[ac4 + 2][arow] = av.z;
        As[ac4 + 3][arow] = av.w;
        *(float4*)&Bs[brow][bc4] = bv;
        __syncthreads();
#pragma unroll
        for (int kk = 0; kk < 8; kk++) {
            float a[8], bb[8];
            *(float4*)a        = *(const float4*)&As[kk][ty * 8];
            *(float4*)(a + 4)  = *(const float4*)&As[kk][ty * 8 + 4];
            *(float4*)bb       = *(const float4*)&Bs[kk][tx * 8];
            *(float4*)(bb + 4) = *(const float4*)&Bs[kk][tx * 8 + 4];
#pragma unroll
            for (int i = 0; i < 8; i++)
#pragma unroll
                for (int j = 0; j < 8; j++) acc[i][j] += a[i] * bb[j];
        }
        __syncthreads();
    }
#pragma unroll
    for (int jq = 0; jq < 2; jq++) {
        int n = n0 + tx * 8 + jq * 4;
        float4 bz = make_float4(0.f, 0.f, 0.f, 0.f);
        if (bias) bz = *(const float4*)(bias + n);
#pragma unroll
        for (int i = 0; i < 8; i++) {
            int m = m0 + ty * 8 + i;
            float4 o;
            o.x = acc[i][jq * 4 + 0] + bz.x;
            o.y = acc[i][jq * 4 + 1] + bz.y;
            o.z = acc[i][jq * 4 + 2] + bz.z;
            o.w = acc[i][jq * 4 + 3] + bz.w;
            if (resid) {
                float4 rv = *(const float4*)(resid + (size_t)m * N + n);
                o.x += rv.x; o.y += rv.y; o.z += rv.z; o.w += rv.w;
            }
            *(float4*)(C + (size_t)m * N + n) = o;
        }
    }
}

// ---------------- grid barrier (monotonic, replay-safe) ----------------
__device__ __forceinline__ void gsync() {
    __syncthreads();
    if (threadIdx.x == 0) {
        __threadfence();
        unsigned long long old = atomicAdd(&g_bar, 1ULL);
        unsigned long long target = (old / GS + 1ULL) * (unsigned long long)GS;
        while (*((volatile unsigned long long*)&g_bar) < target) __nanosleep(64);
        __threadfence();
    }
    __syncthreads();
}

// ---------------- scan stage machinery (verified tile math from R2) ----------------
__device__ __forceinline__ float lecun_tanh(float v) { return 1.7159f * tanhf(0.666f * v); }

// MODE 0: out = lecun_tanh(A@W + add[row-strided]) ; MODE 1: out = lecun_tanh(A@W + bias)
template <int MODE>
__device__ void scan_stage(const float* __restrict__ A, int K,
                           const float* __restrict__ W, int ldw,
                           const float* __restrict__ add, int add_stride,
                           float* __restrict__ out, int ldo, int n0,
                           float (*a_s)[32], float (*w_s)[16], float (*red)[32][17]) {
    int tid = threadIdx.x;
    int ks = tid >> 5, lane = tid & 31;
    int cg = lane >> 2, rg = lane & 3;
    int arow = tid & 31;
    int akq  = (tid >> 5) * 8;
    int wrow = tid >> 2;
    int wc4  = (tid & 3) * 4;

    float acc0[8], acc1[8];
#pragma unroll
    for (int r = 0; r < 8; r++) { acc0[r] = 0.f; acc1[r] = 0.f; }

    for (int k0 = 0; k0 < K; k0 += 64) {
        float4 av0 = *(const float4*)(A + (size_t)arow * K + k0 + akq);
        float4 av1 = *(const float4*)(A + (size_t)arow * K + k0 + akq + 4);
        a_s[akq + 0][arow] = av0.x;
        a_s[akq + 1][arow] = av0.y;
        a_s[akq + 2][arow] = av0.z;
        a_s[akq + 3][arow] = av0.w;
        a_s[akq + 4][arow] = av1.x;
        a_s[akq + 5][arow] = av1.y;
        a_s[akq + 6][arow] = av1.z;
        a_s[akq + 7][arow] = av1.w;
        float4 wv = *(const float4*)(W + (size_t)(k0 + wrow) * ldw + n0 + wc4);
        *(float4*)&w_s[wrow][wc4] = wv;
        __syncthreads();
#pragma unroll
        for (int i = 0; i < 8; i++) {
            int kk = ks + i * 8;
            float2 w2 = *(const float2*)&w_s[kk][cg * 2];
            float4 a0 = *(const float4*)&a_s[kk][rg * 8];
            float4 a1 = *(const float4*)&a_s[kk][rg * 8 + 4];
            float ar[8] = {a0.x, a0.y, a0.z, a0.w, a1.x, a1.y, a1.z, a1.w};
#pragma unroll
            for (int r = 0; r < 8; r++) {
                acc0[r] += ar[r] * w2.x;
                acc1[r] += ar[r] * w2.y;
            }
        }
        __syncthreads();
    }

#pragma unroll
    for (int r = 0; r < 8; r++) {
        red[ks][lane][r]     = acc0[r];
        red[ks][lane][8 + r] = acc1[r];
    }
    __syncthreads();

#pragma unroll
    for (int q = 0; q < 2; q++) {
        int o = tid * 2 + q;
        int row = o >> 4, col = o & 15;
        int l2 = (col >> 1) * 4 + (row >> 3);
        int sl = (col & 1) * 8 + (row & 7);
        float v = 0.f;
#pragma unroll
        for (int s = 0; s < 8; s++) v += red[s][l2][sl];
        if (MODE == 0) v += add[(size_t)row * add_stride + n0 + col];
        else           v += add[n0 + col];
        v = lecun_tanh(v);
        out[(size_t)row * ldo + n0 + col] = v;
    }
    __syncthreads();
}

// 4-head GEMM tile + fused CfC pointwise update (4 u-cols per call)
__device__ void head_stage(const float* __restrict__ A,
                           const float* __restrict__ hw0, const float* __restrict__ hw1,
                           const float* __restrict__ hw2, const float* __restrict__ hw3,
                           const float* __restrict__ hb0, const float* __restrict__ hb1,
                           const float* __restrict__ hb2, const float* __restrict__ hb3,
                           const float* __restrict__ ts, int t, int n4,
                           float* __restrict__ h, float* __restrict__ outb,
                           float (*a_s)[32], float (*w_s)[16], float (*red)[32][17],
                           float (*sv)[17]) {
    const int K = BBu;
    int tid = threadIdx.x;
    int ks = tid >> 5, lane = tid & 31;
    int cg = lane >> 2, rg = lane & 3;
    int arow = tid & 31;
    int akq  = (tid >> 5) * 8;
    int wrow = tid >> 2;
    int whd  = tid & 3;
    const float* Wh = (whd == 0) ? hw0 : (whd == 1) ? hw1 : (whd == 2) ? hw2 : hw3;

    float acc0[8], acc1[8];
#pragma unroll
    for (int r = 0; r < 8; r++) { acc0[r] = 0.f; acc1[r] = 0.f; }

    for (int k0 = 0; k0 < K; k0 += 64) {
        float4 av0 = *(const float4*)(A + (size_t)arow * K + k0 + akq);
        float4 av1 = *(const float4*)(A + (size_t)arow * K + k0 + akq + 4);
        a_s[akq + 0][arow] = av0.x;
        a_s[akq + 1][arow] = av0.y;
        a_s[akq + 2][arow] = av0.z;
        a_s[akq + 3][arow] = av0.w;
        a_s[akq + 4][arow] = av1.x;
        a_s[akq + 5][arow] = av1.y;
        a_s[akq + 6][arow] = av1.z;
        a_s[akq + 7][arow] = av1.w;
        float4 wv = *(const float4*)(Wh + (size_t)(k0 + wrow) * Uc + n4);
        *(float4*)&w_s[wrow][whd * 4] = wv;
        __syncthreads();
#pragma unroll
        for (int i = 0; i < 8; i++) {
            int kk = ks + i * 8;
            float2 w2 = *(const float2*)&w_s[kk][cg * 2];
            float4 a0 = *(const float4*)&a_s[kk][rg * 8];
            float4 a1 = *(const float4*)&a_s[kk][rg * 8 + 4];
            float ar[8] = {a0.x, a0.y, a0.z, a0.w, a1.x, a1.y, a1.z, a1.w};
#pragma unroll
            for (int r = 0; r < 8; r++) {
                acc0[r] += ar[r] * w2.x;
                acc1[r] += ar[r] * w2.y;
            }
        }
        __syncthreads();
    }

#pragma unroll
    for (int r = 0; r < 8; r++) {
        red[ks][lane][r]     = acc0[r];
        red[ks][lane][8 + r] = acc1[r];
    }
    __syncthreads();

#pragma unroll
    for (int q = 0; q < 2; q++) {
        int o = tid * 2 + q;
        int row = o >> 4, col = o & 15;
        int l2 = (col >> 1) * 4 + (row >> 3);
        int sl = (col & 1) * 8 + (row & 7);
        float v = 0.f;
#pragma unroll
        for (int s = 0; s < 8; s++) v += red[s][l2][sl];
        int head = col >> 2, c = col & 3;
        const float* hb = (head == 0) ? hb0 : (head == 1) ? hb1 : (head == 2) ? hb2 : hb3;
        v += hb[n4 + c];
        sv[row][col] = v;
    }
    __syncthreads();

    if (tid < 128) {
        int row = tid >> 2, c = tid & 3;
        int u = n4 + c;
        float f1  = tanhf(sv[row][c]);
        float f2  = tanhf(sv[row][4 + c]);
        float ta  = sv[row][8 + c];
        float tb  = sv[row][12 + c];
        float tsv = ts[row * Tt + t];
        float z   = ta * tsv + tb;
        float sig = 1.0f / (1.0f + expf(-z));
        float hn  = f1 * (1.0f - sig) + sig * f2;
        h[row * Uc + u] = hn;
        outb[((size_t)row * Tt + t) * Uc + u] = hn;
    }
    __syncthreads();
}

// ---------------- persistent scan: the whole T=512 loop in ONE kernel ----------------
__global__ __launch_bounds__(256, 1) void scan_persistent(
        const float* __restrict__ hidden, const float* __restrict__ px,
        const float* __restrict__ ts,
        const float* __restrict__ W0bot, const float* __restrict__ W1,
        const float* __restrict__ b1,
        const float* __restrict__ hw0, const float* __restrict__ hw1,
        const float* __restrict__ hw2, const float* __restrict__ hw3,
        const float* __restrict__ hb0, const float* __restrict__ hb1,
        const float* __restrict__ hb2, const float* __restrict__ hb3,
        float* __restrict__ h, float* __restrict__ bb1, float* __restrict__ bb2,
        float* __restrict__ outb, float* __restrict__ hfin) {
    __shared__ float a_s[64][32];
    __shared__ float w_s[64][16];
    __shared__ float red[8][32][17];
    __shared__ float sv[32][17];

    int cta = blockIdx.x;

    for (int t = 0; t < Tt; t++) {
        const float* A0 = (t == 0) ? hidden : h;
        if (cta < BBu / 16)
            scan_stage<0>(A0, Uc, W0bot, BBu, px + (size_t)t * BBu, Tt * BBu,
                          bb1, BBu, cta * 16, a_s, w_s, red);
        gsync();
        if (cta < BBu / 16)
            scan_stage<1>(bb1, BBu, W1, BBu, b1, 0,
                          bb2, BBu, cta * 16, a_s, w_s, red);
        gsync();
        // stage 3: 256 tiles of 4 u-columns, distributed over GS CTAs
        head_stage(bb2, hw0, hw1, hw2, hw3, hb0, hb1, hb2, hb3,
                   ts, t, cta * 4, h, outb, a_s, w_s, red, sv);
        if (cta + GS < Uc / 4)
            head_stage(bb2, hw0, hw1, hw2, hw3, hb0, hb1, hb2, hb3,
                       ts, t, (cta + GS) * 4, h, outb, a_s, w_s, red, sv);
        gsync();
    }

    // h_final copy
    for (int i = cta * 256 + threadIdx.x; i < Bn * Uc; i += GS * 256)
        hfin[i] = h[i];
}

// ---------------- orchestration (5 graph nodes total) ----------------
extern "C" void kernel_launch(void* const* d_in, const int* in_sizes, int n_in,
                              void* d_out, int out_size) {
    const float* x      = (const float*)d_in[0];
    const float* ts     = (const float*)d_in[1];
    const float* hidden = (const float*)d_in[2];
    const float* norm_w = (const float*)d_in[3];
    const float* norm_b = (const float*)d_in[4];
    const float* w_in   = (const float*)d_in[5];
    const float* b_in   = (const float*)d_in[6];
    const float* bb_w   = (const float*)d_in[7];
    const float* bb_b   = (const float*)d_in[8];
    const float* w_ff1  = (const float*)d_in[9];
    const float* b_ff1  = (const float*)d_in[10];
    const float* w_ff2  = (const float*)d_in[11];
    const float* b_ff2  = (const float*)d_in[12];
    const float* w_ta   = (const float*)d_in[13];
    const float* b_ta   = (const float*)d_in[14];
    const float* w_tb   = (const float*)d_in[15];
    const float* b_tb   = (const float*)d_in[16];
    const float* w_out  = (const float*)d_in[17];
    const float* b_out  = (const float*)d_in[18];
    float* y = (float*)d_out;

    float *xn, *cfcx, *px, *outb, *h, *bb1, *bb2;
    cudaGetSymbolAddress((void**)&xn, g_xn);
    cudaGetSymbolAddress((void**)&cfcx, g_cfcx);
    cudaGetSymbolAddress((void**)&px, g_px);
    cudaGetSymbolAddress((void**)&outb, g_cfcout);
    cudaGetSymbolAddress((void**)&h, g_h);
    cudaGetSymbolAddress((void**)&bb1, g_bb1);
    cudaGetSymbolAddress((void**)&bb2, g_bb2);

    // 1) LayerNorm
    ln_kernel<<<NTOK, 256>>>(x, norm_w, norm_b, xn);

    // 2) cfc_x = xn @ w_in + b_in     [16384,1024]
    {
        dim3 g(Dm / 128, NTOK / 128);
        sgemm_k<<<g, 256>>>(xn, w_in, b_in, nullptr, cfcx, NTOK, Dm, Dm);
    }
    // 3) px = cfc_x @ W0_top + bb_b[0]   [16384,2048]
    {
        dim3 g(BBu / 128, NTOK / 128);
        sgemm_k<<<g, 256>>>(cfcx, bb_w, bb_b, nullptr, px, NTOK, BBu, Dm);
    }

    // 4) persistent scan (entire T loop, software grid barriers)
    const float* W0bot = bb_w + (size_t)Dm * BBu;
    const float* W1    = bb_w + (size_t)BBu * BBu;
    const float* b1    = bb_b + BBu;
    scan_persistent<<<GS, 256>>>(hidden, px, ts, W0bot, W1, b1,
                                 w_ff1, w_ff2, w_ta, w_tb,
                                 b_ff1, b_ff2, b_ta, b_tb,
                                 h, bb1, bb2, outb, y + (size_t)NTOK * Dm);

    // 5) y = x + cfc_out @ w_out + b_out
    {
        dim3 g(Dm / 128, NTOK / 128);
        sgemm_k<<<g, 256>>>(outb, w_out, b_out, x, y, NTOK, Dm, Dm);
    }
}

// round 10
// speedup vs baseline: 1.2767x; 1.2767x over previous
#include <cuda_runtime.h>
#include <math.h>

#define Bn   32
#define Tt   512
#define Dm   1024
#define Uc   1024
#define BBu  2048
#define NTOK 16384   // Bn*Tt
#define GS   148     // persistent scan grid (<= SM count -> co-resident)
#define STH  512     // scan threads per CTA (16 warps)

// ---------------- scratch (device globals; no allocs allowed) ----------------
__device__ float g_xn[NTOK * Dm];
__device__ float g_cfcx[NTOK * Dm];
__device__ float g_px[NTOK * BBu];
__device__ float g_cfcout[NTOK * Uc];
__device__ float g_h[Bn * Uc];
__device__ float g_bb1[Bn * BBu];
__device__ float g_bb2[Bn * BBu];
__device__ unsigned long long g_bar;     // monotonic grid-barrier counter

// ---------------- LayerNorm ----------------
__global__ __launch_bounds__(256) void ln_kernel(const float* __restrict__ x,
                                                 const float* __restrict__ w,
                                                 const float* __restrict__ b,
                                                 float* __restrict__ xn) {
    int row = blockIdx.x;
    int t = threadIdx.x;
    const float4* xr = (const float4*)(x + (size_t)row * Dm);
    float4 v = xr[t];
    float s  = v.x + v.y + v.z + v.w;
    float ss = v.x * v.x + v.y * v.y + v.z * v.z + v.w * v.w;
#pragma unroll
    for (int o = 16; o > 0; o >>= 1) {
        s  += __shfl_xor_sync(0xffffffffu, s, o);
        ss += __shfl_xor_sync(0xffffffffu, ss, o);
    }
    __shared__ float sred[16];
    __shared__ float s_mu, s_rs;
    int warp = t >> 5, lane = t & 31;
    if (lane == 0) { sred[warp] = s; sred[8 + warp] = ss; }
    __syncthreads();
    if (t == 0) {
        float S = 0.f, SS = 0.f;
#pragma unroll
        for (int i = 0; i < 8; i++) { S += sred[i]; SS += sred[8 + i]; }
        float mu = S * (1.0f / Dm);
        float var = SS * (1.0f / Dm) - mu * mu;
        s_mu = mu;
        s_rs = rsqrtf(var + 1e-5f);
    }
    __syncthreads();
    float mu = s_mu, rs = s_rs;
    float4 wv = ((const float4*)w)[t];
    float4 bv = ((const float4*)b)[t];
    float4 o;
    o.x = (v.x - mu) * rs * wv.x + bv.x;
    o.y = (v.y - mu) * rs * wv.y + bv.y;
    o.z = (v.z - mu) * rs * wv.z + bv.z;
    o.w = (v.w - mu) * rs * wv.w + bv.w;
    ((float4*)(xn + (size_t)row * Dm))[t] = o;
}

// ---------------- big SGEMM: C[M,N] = A[M,K]@B[K,N] (+bias) (+resid) ----------------
__global__ __launch_bounds__(256) void sgemm_k(const float* __restrict__ A,
                                               const float* __restrict__ B,
                                               const float* __restrict__ bias,
                                               const float* __restrict__ resid,
                                               float* __restrict__ C,
                                               int M, int N, int K) {
    __shared__ float As[8][128];
    __shared__ float Bs[8][128];
    int tid = threadIdx.x;
    int m0 = blockIdx.y * 128, n0 = blockIdx.x * 128;
    int tx = tid & 15, ty = tid >> 4;
    float acc[8][8];
#pragma unroll
    for (int i = 0; i < 8; i++)
#pragma unroll
        for (int j = 0; j < 8; j++) acc[i][j] = 0.f;

    int arow = tid >> 1, ac4 = (tid & 1) * 4;
    int brow = tid >> 5, bc4 = (tid & 31) * 4;
    const float* Ap = A + (size_t)(m0 + arow) * K + ac4;
    const float* Bp = B + (size_t)brow * N + n0 + bc4;

    for (int k0 = 0; k0 < K; k0 += 8) {
        float4 av = *(const float4*)(Ap + k0);
        float4 bv = *(const float4*)(Bp + (size_t)k0 * N);
        As[ac4 + 0][arow] = av.x;
        As[ac4 + 1][arow] = av.y;
        As[ac4 + 2][arow] = av.z;
        As[ac4 + 3][arow] = av.w;
        *(float4*)&Bs[brow][bc4] = bv;
        __syncthreads();
#pragma unroll
        for (int kk = 0; kk < 8; kk++) {
            float a[8], bb[8];
            *(float4*)a        = *(const float4*)&As[kk][ty * 8];
            *(float4*)(a + 4)  = *(const float4*)&As[kk][ty * 8 + 4];
            *(float4*)bb       = *(const float4*)&Bs[kk][tx * 8];
            *(float4*)(bb + 4) = *(const float4*)&Bs[kk][tx * 8 + 4];
#pragma unroll
            for (int i = 0; i < 8; i++)
#pragma unroll
                for (int j = 0; j < 8; j++) acc[i][j] += a[i] * bb[j];
        }
        __syncthreads();
    }
#pragma unroll
    for (int jq = 0; jq < 2; jq++) {
        int n = n0 + tx * 8 + jq * 4;
        float4 bz = make_float4(0.f, 0.f, 0.f, 0.f);
        if (bias) bz = *(const float4*)(bias + n);
#pragma unroll
        for (int i = 0; i < 8; i++) {
            int m = m0 + ty * 8 + i;
            float4 o;
            o.x = acc[i][jq * 4 + 0] + bz.x;
            o.y = acc[i][jq * 4 + 1] + bz.y;
            o.z = acc[i][jq * 4 + 2] + bz.z;
            o.w = acc[i][jq * 4 + 3] + bz.w;
            if (resid) {
                float4 rv = *(const float4*)(resid + (size_t)m * N + n);
                o.x += rv.x; o.y += rv.y; o.z += rv.z; o.w += rv.w;
            }
            *(float4*)(C + (size_t)m * N + n) = o;
        }
    }
}

// ---------------- grid barrier (monotonic, replay-safe) ----------------
__device__ __forceinline__ void gsync() {
    __syncthreads();
    if (threadIdx.x == 0) {
        __threadfence();
        unsigned long long old = atomicAdd(&g_bar, 1ULL);
        unsigned long long target = (old / GS + 1ULL) * (unsigned long long)GS;
        while (*((volatile unsigned long long*)&g_bar) < target) __nanosleep(64);
        __threadfence();
    }
    __syncthreads();
}

// ---------------- scan stage machinery (512 thr, 16-way K-split, double-buffered) ----------------
__device__ __forceinline__ float lecun_tanh(float v) { return 1.7159f * tanhf(0.666f * v); }

// MODE 0: out = lecun_tanh(A@W + add[row-strided]) ; MODE 1: out = lecun_tanh(A@W + bias)
template <int MODE>
__device__ void scan_stage(const float* __restrict__ A, int K,
                           const float* __restrict__ W, int ldw,
                           const float* __restrict__ add, int add_stride,
                           float* __restrict__ out, int ldo, int n0,
                           float (*a_s)[64][32], float (*w_s)[64][16],
                           float (*red)[32][17]) {
    int tid = threadIdx.x;
    int ks = tid >> 5, lane = tid & 31;          // 16 warps
    int cg = lane >> 2, rg = lane & 3;
    int arow = tid & 31;
    int akq  = (tid >> 5) * 4;                   // 16 groups of 4 k
    int wrow = tid >> 3;                         // 0..63
    int wc2  = (tid & 7) * 2;                    // 0,2,..,14

    float acc0[8], acc1[8];
#pragma unroll
    for (int r = 0; r < 8; r++) { acc0[r] = 0.f; acc1[r] = 0.f; }

    const float* Arow = A + (size_t)arow * K;
    int nch = K >> 6;
    float4 pa = *(const float4*)(Arow + akq);
    float2 pw = *(const float2*)(W + (size_t)wrow * ldw + n0 + wc2);

    for (int c = 0; c < nch; c++) {
        int buf = c & 1;
        a_s[buf][akq + 0][arow] = pa.x;
        a_s[buf][akq + 1][arow] = pa.y;
        a_s[buf][akq + 2][arow] = pa.z;
        a_s[buf][akq + 3][arow] = pa.w;
        *(float2*)&w_s[buf][wrow][wc2] = pw;
        if (c + 1 < nch) {
            int k0 = (c + 1) << 6;
            pa = *(const float4*)(Arow + k0 + akq);
            pw = *(const float2*)(W + (size_t)(k0 + wrow) * ldw + n0 + wc2);
        }
        __syncthreads();
#pragma unroll
        for (int i = 0; i < 4; i++) {
            int kk = ks + i * 16;
            float2 w2 = *(const float2*)&w_s[buf][kk][cg * 2];
            float4 a0 = *(const float4*)&a_s[buf][kk][rg * 8];
            float4 a1 = *(const float4*)&a_s[buf][kk][rg * 8 + 4];
            float ar[8] = {a0.x, a0.y, a0.z, a0.w, a1.x, a1.y, a1.z, a1.w};
#pragma unroll
            for (int r = 0; r < 8; r++) {
                acc0[r] += ar[r] * w2.x;
                acc1[r] += ar[r] * w2.y;
            }
        }
        // no trailing sync: next iter writes the other buffer; hazard separated by next sync
    }
    __syncthreads();   // all compute done before red aliases a_s/w_s

#pragma unroll
    for (int r = 0; r < 8; r++) {
        red[ks][lane][r]     = acc0[r];
        red[ks][lane][8 + r] = acc1[r];
    }
    __syncthreads();

    {
        int o = tid;                       // 0..511, one output each
        int row = o >> 4, col = o & 15;
        int l2 = (col >> 1) * 4 + (row >> 3);
        int sl = (col & 1) * 8 + (row & 7);
        float v = 0.f;
#pragma unroll
        for (int s = 0; s < 16; s++) v += red[s][l2][sl];
        if (MODE == 0) v += add[(size_t)row * add_stride + n0 + col];
        else           v += add[n0 + col];
        v = lecun_tanh(v);
        out[(size_t)row * ldo + n0 + col] = v;
    }
    __syncthreads();   // red region reused as a_s by the next stage
}

// 4-head GEMM tile + fused CfC pointwise update (4 u-cols x 4 heads per call)
__device__ void head_stage(const float* __restrict__ A,
                           const float* __restrict__ hw0, const float* __restrict__ hw1,
                           const float* __restrict__ hw2, const float* __restrict__ hw3,
                           const float* __restrict__ hb0, const float* __restrict__ hb1,
                           const float* __restrict__ hb2, const float* __restrict__ hb3,
                           const float* __restrict__ ts, int t, int n4,
                           float* __restrict__ h, float* __restrict__ outb,
                           float (*a_s)[64][32], float (*w_s)[64][16],
                           float (*red)[32][17], float (*sv)[17]) {
    const int K = BBu;
    int tid = threadIdx.x;
    int ks = tid >> 5, lane = tid & 31;
    int cg = lane >> 2, rg = lane & 3;
    int arow = tid & 31;
    int akq  = (tid >> 5) * 4;
    int wrow = tid >> 3;                    // 0..63
    int wcol = (tid & 7) * 2;               // 0..14 even: col = head*4 + c
    int whd  = wcol >> 2;
    int wcin = wcol & 3;
    const float* Wh = (whd == 0) ? hw0 : (whd == 1) ? hw1 : (whd == 2) ? hw2 : hw3;

    float acc0[8], acc1[8];
#pragma unroll
    for (int r = 0; r < 8; r++) { acc0[r] = 0.f; acc1[r] = 0.f; }

    const float* Arow = A + (size_t)arow * K;
    int nch = K >> 6;
    float4 pa = *(const float4*)(Arow + akq);
    float2 pw = *(const float2*)(Wh + (size_t)wrow * Uc + n4 + wcin);

    for (int c = 0; c < nch; c++) {
        int buf = c & 1;
        a_s[buf][akq + 0][arow] = pa.x;
        a_s[buf][akq + 1][arow] = pa.y;
        a_s[buf][akq + 2][arow] = pa.z;
        a_s[buf][akq + 3][arow] = pa.w;
        *(float2*)&w_s[buf][wrow][wcol] = pw;
        if (c + 1 < nch) {
            int k0 = (c + 1) << 6;
            pa = *(const float4*)(Arow + k0 + akq);
            pw = *(const float2*)(Wh + (size_t)(k0 + wrow) * Uc + n4 + wcin);
        }
        __syncthreads();
#pragma unroll
        for (int i = 0; i < 4; i++) {
            int kk = ks + i * 16;
            float2 w2 = *(const float2*)&w_s[buf][kk][cg * 2];
            float4 a0 = *(const float4*)&a_s[buf][kk][rg * 8];
            float4 a1 = *(const float4*)&a_s[buf][kk][rg * 8 + 4];
            float ar[8] = {a0.x, a0.y, a0.z, a0.w, a1.x, a1.y, a1.z, a1.w};
#pragma unroll
            for (int r = 0; r < 8; r++) {
                acc0[r] += ar[r] * w2.x;
                acc1[r] += ar[r] * w2.y;
            }
        }
    }
    __syncthreads();

#pragma unroll
    for (int r = 0; r < 8; r++) {
        red[ks][lane][r]     = acc0[r];
        red[ks][lane][8 + r] = acc1[r];
    }
    __syncthreads();

    {
        int o = tid;
        int row = o >> 4, col = o & 15;
        int l2 = (col >> 1) * 4 + (row >> 3);
        int sl = (col & 1) * 8 + (row & 7);
        float v = 0.f;
#pragma unroll
        for (int s = 0; s < 16; s++) v += red[s][l2][sl];
        int head = col >> 2, c = col & 3;
        const float* hb = (head == 0) ? hb0 : (head == 1) ? hb1 : (head == 2) ? hb2 : hb3;
        v += hb[n4 + c];
        sv[row][col] = v;
    }
    __syncthreads();

    if (tid < 128) {
        int row = tid >> 2, c = tid & 3;
        int u = n4 + c;
        float f1  = tanhf(sv[row][c]);
        float f2  = tanhf(sv[row][4 + c]);
        float ta  = sv[row][8 + c];
        float tb  = sv[row][12 + c];
        float tsv = ts[row * Tt + t];
        float z   = ta * tsv + tb;
        float sig = 1.0f / (1.0f + expf(-z));
        float hn  = f1 * (1.0f - sig) + sig * f2;
        h[row * Uc + u] = hn;
        outb[((size_t)row * Tt + t) * Uc + u] = hn;
    }
    __syncthreads();
}

// ---------------- persistent scan ----------------
// smem pool (floats): [0, 4096)  a_s[2][64][32]
//                     [4096,6144) w_s[2][64][16]
//                     [0, 8704)  red[16][32][17]   (aliases a_s/w_s; sync-separated)
//                     [8704,9248) sv[32][17]
__global__ __launch_bounds__(STH, 1) void scan_persistent(
        const float* __restrict__ hidden, const float* __restrict__ px,
        const float* __restrict__ ts,
        const float* __restrict__ W0bot, const float* __restrict__ W1,
        const float* __restrict__ b1,
        const float* __restrict__ hw0, const float* __restrict__ hw1,
        const float* __restrict__ hw2, const float* __restrict__ hw3,
        const float* __restrict__ hb0, const float* __restrict__ hb1,
        const float* __restrict__ hb2, const float* __restrict__ hb3,
        float* __restrict__ h, float* __restrict__ bb1, float* __restrict__ bb2,
        float* __restrict__ outb, float* __restrict__ hfin) {
    __shared__ __align__(16) float pool[9248];
    float (*a_s)[64][32] = (float(*)[64][32])pool;
    float (*w_s)[64][16] = (float(*)[64][16])(pool + 4096);
    float (*red)[32][17] = (float(*)[32][17])pool;
    float (*sv)[17]      = (float(*)[17])(pool + 8704);

    int cta = blockIdx.x;

    for (int t = 0; t < Tt; t++) {
        const float* A0 = (t == 0) ? hidden : h;
        if (cta < BBu / 16)
            scan_stage<0>(A0, Uc, W0bot, BBu, px + (size_t)t * BBu, Tt * BBu,
                          bb1, BBu, cta * 16, a_s, w_s, red);
        gsync();
        if (cta < BBu / 16)
            scan_stage<1>(bb1, BBu, W1, BBu, b1, 0,
                          bb2, BBu, cta * 16, a_s, w_s, red);
        gsync();
        head_stage(bb2, hw0, hw1, hw2, hw3, hb0, hb1, hb2, hb3,
                   ts, t, cta * 4, h, outb, a_s, w_s, red, sv);
        if (cta + GS < Uc / 4)
            head_stage(bb2, hw0, hw1, hw2, hw3, hb0, hb1, hb2, hb3,
                       ts, t, (cta + GS) * 4, h, outb, a_s, w_s, red, sv);
        gsync();
    }

    for (int i = cta * STH + threadIdx.x; i < Bn * Uc; i += GS * STH)
        hfin[i] = h[i];
}

// ---------------- orchestration (5 graph nodes total) ----------------
extern "C" void kernel_launch(void* const* d_in, const int* in_sizes, int n_in,
                              void* d_out, int out_size) {
    const float* x      = (const float*)d_in[0];
    const float* ts     = (const float*)d_in[1];
    const float* hidden = (const float*)d_in[2];
    const float* norm_w = (const float*)d_in[3];
    const float* norm_b = (const float*)d_in[4];
    const float* w_in   = (const float*)d_in[5];
    const float* b_in   = (const float*)d_in[6];
    const float* bb_w   = (const float*)d_in[7];
    const float* bb_b   = (const float*)d_in[8];
    const float* w_ff1  = (const float*)d_in[9];
    const float* b_ff1  = (const float*)d_in[10];
    const float* w_ff2  = (const float*)d_in[11];
    const float* b_ff2  = (const float*)d_in[12];
    const float* w_ta   = (const float*)d_in[13];
    const float* b_ta   = (const float*)d_in[14];
    const float* w_tb   = (const float*)d_in[15];
    const float* b_tb   = (const float*)d_in[16];
    const float* w_out  = (const float*)d_in[17];
    const float* b_out  = (const float*)d_in[18];
    float* y = (float*)d_out;

    float *xn, *cfcx, *px, *outb, *h, *bb1, *bb2;
    cudaGetSymbolAddress((void**)&xn, g_xn);
    cudaGetSymbolAddress((void**)&cfcx, g_cfcx);
    cudaGetSymbolAddress((void**)&px, g_px);
    cudaGetSymbolAddress((void**)&outb, g_cfcout);
    cudaGetSymbolAddress((void**)&h, g_h);
    cudaGetSymbolAddress((void**)&bb1, g_bb1);
    cudaGetSymbolAddress((void**)&bb2, g_bb2);

    // 1) LayerNorm
    ln_kernel<<<NTOK, 256>>>(x, norm_w, norm_b, xn);

    // 2) cfc_x = xn @ w_in + b_in     [16384,1024]
    {
        dim3 g(Dm / 128, NTOK / 128);
        sgemm_k<<<g, 256>>>(xn, w_in, b_in, nullptr, cfcx, NTOK, Dm, Dm);
    }
    // 3) px = cfc_x @ W0_top + bb_b[0]   [16384,2048]
    {
        dim3 g(BBu / 128, NTOK / 128);
        sgemm_k<<<g, 256>>>(cfcx, bb_w, bb_b, nullptr, px, NTOK, BBu, Dm);
    }

    // 4) persistent scan (entire T loop, software grid barriers)
    const float* W0bot = bb_w + (size_t)Dm * BBu;
    const float* W1    = bb_w + (size_t)BBu * BBu;
    const float* b1    = bb_b + BBu;
    scan_persistent<<<GS, STH>>>(hidden, px, ts, W0bot, W1, b1,
                                 w_ff1, w_ff2, w_ta, w_tb,
                                 b_ff1, b_ff2, b_ta, b_tb,
                                 h, bb1, bb2, outb, y + (size_t)NTOK * Dm);

    // 5) y = x + cfc_out @ w_out + b_out
    {
        dim3 g(Dm / 128, NTOK / 128);
        sgemm_k<<<g, 256>>>(outb, w_out, b_out, x, y, NTOK, Dm, Dm);
    }
}